// round 3
// baseline (speedup 1.0000x reference)
#include <cuda_runtime.h>

#define BATCH 64
#define NSTEPS 2000
#define TAPS 64
#define NTHREADS 128
#define SYM_PERIOD 100

__global__ void __launch_bounds__(NTHREADS, 1)
rls_kernel(const float* __restrict__ x_seq,
           const float* __restrict__ d_seq,
           const float* __restrict__ lambdas,
           float* __restrict__ y_out,
           float* __restrict__ w_out)
{
    const int b    = blockIdx.x;
    const int tid  = threadIdx.x;
    const int i    = tid >> 1;   // row 0..63
    const int c    = tid & 1;    // column-half 0/1
    const int lane = tid & 31;
    const int warp = tid >> 5;

    __shared__ __align__(16) float xbuf[2][TAPS];
    __shared__ __align__(16) float Pxbuf[2][TAPS];
    __shared__ float red[2][4][2];
    __shared__ float dbuf[2];
    __shared__ float lambuf[2];
    __shared__ float tile[TAPS][TAPS + 1];   // transpose scratch (padded)

    // P row-half in registers: row i, cols [32c, 32c+32)
    float P[32];
#pragma unroll
    for (int j = 0; j < 32; j++) P[j] = 0.0f;
    if ((i >> 5) == c) P[i & 31] = 1.0f;   // identity diagonal
    float w = 0.0f;

    const float* xb = x_seq + (size_t)b * NSTEPS * TAPS;
    const float* db = d_seq + (size_t)b * NSTEPS;

    // preload step 0
    if (tid < TAPS) xbuf[0][tid] = xb[tid];
    if (tid == 64)  dbuf[0]      = db[0];
    if (tid == 65)  lambuf[0]    = lambdas[0];
    __syncthreads();

    for (int t = 0; t < NSTEPS; t++) {
        const int buf  = t & 1;
        const int nbuf = buf ^ 1;

        // pre-barrier register reads of this step's scalars (ordered against
        // the producing stash by barrier t-1; overwritten only after barrier t)
        const float d_r   = dbuf[buf];
        const float lam_r = lambuf[buf];

        // prefetch t+1 from global
        float xpre = 0.0f, dpre = 0.0f, lampre = 0.0f;
        if (t + 1 < NSTEPS) {
            if (tid < TAPS) xpre   = __ldg(xb + (size_t)(t + 1) * TAPS + tid);
            if (tid == 64)  dpre   = __ldg(db + t + 1);
            if (tid == 65)  lampre = __ldg(lambdas + t + 1);
        }

        // Px partial over this thread's 32-col chunk
        const float4* xs = (const float4*)(xbuf[buf] + c * 32);
        float a0 = 0.f, a1 = 0.f, a2 = 0.f, a3 = 0.f;
#pragma unroll
        for (int k = 0; k < 8; k++) {
            const float4 q = xs[k];
            a0 = fmaf(P[4 * k + 0], q.x, a0);
            a1 = fmaf(P[4 * k + 1], q.y, a1);
            a2 = fmaf(P[4 * k + 2], q.z, a2);
            a3 = fmaf(P[4 * k + 3], q.w, a3);
        }
        const float pxp = (a0 + a1) + (a2 + a3);
        const float Pxi = pxp + __shfl_xor_sync(0xffffffffu, pxp, 1);

        const float xi = xbuf[buf][i];
        float s1 = xi * pxp;                    // -> x·Px
        float s2 = (c == 0) ? w * xi : 0.0f;    // -> y_hat
#pragma unroll
        for (int off = 16; off >= 1; off >>= 1) {
            s1 += __shfl_xor_sync(0xffffffffu, s1, off);
            s2 += __shfl_xor_sync(0xffffffffu, s2, off);
        }
        if (lane == 0) { red[buf][warp][0] = s1; red[buf][warp][1] = s2; }
        if (c == 0)    Pxbuf[buf][i] = Pxi;

        // stash prefetched t+1 inputs
        if (t + 1 < NSTEPS) {
            if (tid < TAPS) xbuf[nbuf][tid] = xpre;
            if (tid == 64)  dbuf[nbuf]      = dpre;
            if (tid == 65)  lambuf[nbuf]    = lampre;
        }

        __syncthreads();   // the one mandatory barrier per step

        // scalar stage (redundant on all threads)
        float lam = fminf(fmaxf(lam_r, 1e-4f), 0.9999f);
        const float xPx  = (red[buf][0][0] + red[buf][1][0]) +
                           (red[buf][2][0] + red[buf][3][0]);
        const float yhat = (red[buf][0][1] + red[buf][1][1]) +
                           (red[buf][2][1] + red[buf][3][1]);
        const float denom = lam + xPx;
        const float g     = Pxi / denom;
        const float e     = d_r - yhat;
        w = fmaf(g, e, w);
        if (tid == 0) y_out[(size_t)b * NSTEPS + t] = yhat;

        // P rank-1 update in registers: P = (P - g*Px_j) / lam
        const float rlam = 1.0f / lam;
        const float4* ps = (const float4*)(Pxbuf[buf] + c * 32);
#pragma unroll
        for (int k = 0; k < 8; k++) {
            const float4 q = ps[k];
            P[4 * k + 0] = fmaf(-g, q.x, P[4 * k + 0]) * rlam;
            P[4 * k + 1] = fmaf(-g, q.y, P[4 * k + 1]) * rlam;
            P[4 * k + 2] = fmaf(-g, q.z, P[4 * k + 2]) * rlam;
            P[4 * k + 3] = fmaf(-g, q.w, P[4 * k + 3]) * rlam;
        }

        // ---- periodic symmetrization: kills the undamped antisymmetric
        //      error mode (E' = E/lam) before it can grow past ~2.7x ----
        if ((t % SYM_PERIOD) == (SYM_PERIOD - 1)) {
#pragma unroll
            for (int j = 0; j < 32; j++) tile[i][32 * c + j] = P[j];
            __syncthreads();
#pragma unroll
            for (int j = 0; j < 32; j++)
                P[j] = 0.5f * (P[j] + tile[32 * c + j][i]);
            __syncthreads();
        }
    }

    if (c == 0) w_out[(size_t)b * TAPS + i] = w;
}

extern "C" void kernel_launch(void* const* d_in, const int* in_sizes, int n_in,
                              void* d_out, int out_size)
{
    const float* x_seq   = (const float*)d_in[0];
    const float* d_seq   = (const float*)d_in[1];
    const float* lambdas = (const float*)d_in[2];
    float* y_out = (float*)d_out;                          // [64, 2000]
    float* w_out = (float*)d_out + (size_t)BATCH * NSTEPS; // [64, 64]
    rls_kernel<<<BATCH, NTHREADS>>>(x_seq, d_seq, lambdas, y_out, w_out);
}

// round 4
// speedup vs baseline: 1.2091x; 1.2091x over previous
#include <cuda_runtime.h>
#include <cstdint>

#define BATCH 64
#define NSTEPS 2000
#define TAPS 64
#define NTHREADS 128
#define SYM_PERIOD 100
#define CHUNK 16
#define NCHUNK (NSTEPS / CHUNK)   // 125

__device__ __forceinline__ void cp16(uint32_t dst_smem, const void* src_gmem) {
    asm volatile("cp.async.cg.shared.global [%0], [%1], 16;\n"
                 :: "r"(dst_smem), "l"(src_gmem));
}
__device__ __forceinline__ void cp_commit() {
    asm volatile("cp.async.commit_group;\n");
}
template <int N>
__device__ __forceinline__ void cp_wait() {
    asm volatile("cp.async.wait_group %0;\n" :: "n"(N));
}

__global__ void __launch_bounds__(NTHREADS, 1)
rls_kernel(const float* __restrict__ x_seq,
           const float* __restrict__ d_seq,
           const float* __restrict__ lambdas,
           float* __restrict__ y_out,
           float* __restrict__ w_out)
{
    const int b    = blockIdx.x;
    const int tid  = threadIdx.x;
    const int i    = tid >> 1;   // row 0..63
    const int c    = tid & 1;    // column-half 0/1
    const int lane = tid & 31;
    const int warp = tid >> 5;

    __shared__ __align__(16) float xc[2][CHUNK][TAPS];   // 8 KB
    __shared__ __align__(16) float dc[2][CHUNK];
    __shared__ __align__(16) float lc[2][CHUNK];
    __shared__ __align__(16) float Uxbuf[2][TAPS];
    __shared__ float red[2][4][2];
    __shared__ float tile[TAPS][TAPS + 1];               // transpose scratch

    // Q row-half in registers: row i, cols [32c, 32c+32).  P = sigma * Q.
    float Q[32];
#pragma unroll
    for (int j = 0; j < 32; j++) Q[j] = 0.0f;
    if ((i >> 5) == c) Q[i & 31] = 1.0f;
    float w = 0.0f;
    float sigma = 1.0f;

    const float* xb = x_seq + (size_t)b * NSTEPS * TAPS;
    const float* db = d_seq + (size_t)b * NSTEPS;

    const uint32_t xc_s = (uint32_t)__cvta_generic_to_shared(&xc[0][0][0]);
    const uint32_t dc_s = (uint32_t)__cvta_generic_to_shared(&dc[0][0]);
    const uint32_t lc_s = (uint32_t)__cvta_generic_to_shared(&lc[0][0]);

    // async-load one chunk into buffer `cb`
    auto issue_chunk = [&](int ck, int cb) {
#pragma unroll
        for (int j = 0; j < 2; j++)   // 4 KB of x per chunk = 2 x 16B per thread
            cp16(xc_s + cb * (CHUNK * TAPS * 4) + j * 2048 + tid * 16,
                 xb + (size_t)ck * CHUNK * TAPS + j * 512 + tid * 4);
        if (tid < 4)
            cp16(dc_s + cb * (CHUNK * 4) + tid * 16, db + ck * CHUNK + tid * 4);
        else if (tid < 8)
            cp16(lc_s + cb * (CHUNK * 4) + (tid - 4) * 16,
                 lambdas + ck * CHUNK + (tid - 4) * 4);
        cp_commit();
    };

    // prologue: chunk 0 and 1 in flight
    issue_chunk(0, 0);
    issue_chunk(1, 1);
    cp_wait<1>();          // chunk 0 complete
    __syncthreads();

    for (int t = 0; t < NSTEPS; t++) {
        const int s   = t & (CHUNK - 1);
        const int ck  = t >> 4;
        const int cb  = ck & 1;
        const int pb  = t & 1;          // ping-pong for red/Uxbuf

        if (s == 0 && t > 0) {
            if (ck + 1 < NCHUNK) { issue_chunk(ck + 1, cb ^ 1); cp_wait<1>(); }
            else                 { cp_wait<0>(); }
            __syncthreads();    // chunk data visible to all threads
        }

        // this step's scalars, pre-barrier (buffer not overwritten until
        // the next chunk issue, which is ordered after this step's barrier)
        const float d_r   = dc[cb][s];
        const float lam_r = lc[cb][s];

        // ---- u = Q x  (thread's 32-col partial) ----
        const float4* xs = (const float4*)(&xc[cb][s][c * 32]);
        float a0 = 0.f, a1 = 0.f, a2 = 0.f, a3 = 0.f;
#pragma unroll
        for (int k = 0; k < 8; k++) {
            const float4 q = xs[k];
            a0 = fmaf(Q[4 * k + 0], q.x, a0);
            a1 = fmaf(Q[4 * k + 1], q.y, a1);
            a2 = fmaf(Q[4 * k + 2], q.z, a2);
            a3 = fmaf(Q[4 * k + 3], q.w, a3);
        }
        const float pxp = (a0 + a1) + (a2 + a3);
        const float Uxi = pxp + __shfl_xor_sync(0xffffffffu, pxp, 1); // u_i

        const float xi = xc[cb][s][i];
        float s1 = xi * pxp;                    // -> x . u
        float s2 = (c == 0) ? w * xi : 0.0f;    // -> y_hat
#pragma unroll
        for (int off = 16; off >= 1; off >>= 1) {
            s1 += __shfl_xor_sync(0xffffffffu, s1, off);
            s2 += __shfl_xor_sync(0xffffffffu, s2, off);
        }
        if (lane == 0) { red[pb][warp][0] = s1; red[pb][warp][1] = s2; }
        if (c == 0)    Uxbuf[pb][i] = Uxi;

        __syncthreads();   // the one mandatory barrier per step

        // ---- scalar stage (redundant on all threads) ----
        const float lam  = fminf(fmaxf(lam_r, 1e-4f), 0.9999f);
        const float s1t  = (red[pb][0][0] + red[pb][1][0]) +
                           (red[pb][2][0] + red[pb][3][0]);
        const float yhat = (red[pb][0][1] + red[pb][1][1]) +
                           (red[pb][2][1] + red[pb][3][1]);
        const float denom = fmaf(sigma, s1t, lam);     // lam + x'Px
        const float rd    = __fdividef(1.0f, denom);
        const float kk    = sigma * rd;                // g_i = kk * u_i
        const float e     = d_r - yhat;
        w = fmaf(kk * e, Uxi, w);
        if (tid == 0) y_out[(size_t)b * NSTEPS + t] = yhat;
        sigma = sigma / lam;                           // exact: sigma error never damps

        // ---- Q rank-1 update: Q -= kk * u u'  (one FMA per element) ----
        const float m = -kk * Uxi;
        const float4* us = (const float4*)(&Uxbuf[pb][c * 32]);
#pragma unroll
        for (int k = 0; k < 8; k++) {
            const float4 q = us[k];
            Q[4 * k + 0] = fmaf(m, q.x, Q[4 * k + 0]);
            Q[4 * k + 1] = fmaf(m, q.y, Q[4 * k + 1]);
            Q[4 * k + 2] = fmaf(m, q.z, Q[4 * k + 2]);
            Q[4 * k + 3] = fmaf(m, q.w, Q[4 * k + 3]);
        }

        // ---- periodic symmetrization of Q (kills undamped antisym mode) ----
        if ((t % SYM_PERIOD) == (SYM_PERIOD - 1)) {
#pragma unroll
            for (int j = 0; j < 32; j++) tile[i][32 * c + j] = Q[j];
            __syncthreads();
#pragma unroll
            for (int j = 0; j < 32; j++)
                Q[j] = 0.5f * (Q[j] + tile[32 * c + j][i]);
            __syncthreads();
        }
    }

    if (c == 0) w_out[(size_t)b * TAPS + i] = w;
}

extern "C" void kernel_launch(void* const* d_in, const int* in_sizes, int n_in,
                              void* d_out, int out_size)
{
    const float* x_seq   = (const float*)d_in[0];
    const float* d_seq   = (const float*)d_in[1];
    const float* lambdas = (const float*)d_in[2];
    float* y_out = (float*)d_out;                          // [64, 2000]
    float* w_out = (float*)d_out + (size_t)BATCH * NSTEPS; // [64, 64]
    rls_kernel<<<BATCH, NTHREADS>>>(x_seq, d_seq, lambdas, y_out, w_out);
}